// round 2
// baseline (speedup 1.0000x reference)
#include <cuda_runtime.h>

// Shapes (compile-time constants from the reference)
#define NQ     24
#define KTOT   (NQ * NQ)        // 576 quadrature points
#define MSIDE  12
#define MTOT   (MSIDE * MSIDE)  // 144 output locations
#define CI     16
#define CO     16
#define HID    8
#define BATCH  32
#define DECAYF 1296.0f          // (24/4)^4
#define E_F    2.7182818284590452f
#define SPLIT  4                // k-stripes per m

// Scratch: features transposed to k-major: featT[k*512 + b*16 + c]
__device__ float g_featT[KTOT * BATCH * CI];

// ---------------------------------------------------------------------------
// Prep: zero the output and build featT (features is (B, CI, K) row-major)
// ---------------------------------------------------------------------------
__global__ void qc_prep(const float* __restrict__ feats, float* __restrict__ out) {
    int idx = blockIdx.x * blockDim.x + threadIdx.x;
    if (idx < KTOT * BATCH * CI) {
        int k  = idx >> 9;          // /512
        int bc = idx & 511;         // b*16 + c
        g_featT[idx] = feats[bc * KTOT + k];
    }
    if (idx < BATCH * CO * MTOT) out[idx] = 0.0f;
}

// ---------------------------------------------------------------------------
// Main: one (m, stripe) per block; 256 threads = (o, c) pairs.
// ---------------------------------------------------------------------------
__global__ void __launch_bounds__(256, 1)
qc_main(const float* __restrict__ W1g,   // (CO, CI, 2, 8)
        const float* __restrict__ W2g,   // (CO, CI, 8, 8)
        const float* __restrict__ W3g,   // (CO, CI, 8, 1)
        const float* __restrict__ locs,  // (144, 2)
        const float* __restrict__ qn,    // (24,)
        const float* __restrict__ qw,    // (24,)
        float* __restrict__ out)         // (B, CO, M) — pre-zeroed
{
    const int m = blockIdx.x / SPLIT;
    const int s = blockIdx.x % SPLIT;
    const int t = threadIdx.x;
    const int o = t >> 4;
    const int c = t & 15;

    __shared__ float s_nx[KTOT], s_ny[KTOT], s_nw[KTOT];
    __shared__ float s_v[CO * 17];          // kernel values, padded
    __shared__ float s_f[BATCH * 17];       // feature panel,  padded

    // Stage quadrature nodes/weights: k = i*24 + j -> node (qn[j], qn[i]), w = qw[i]*qw[j]
    for (int k = t; k < KTOT; k += 256) {
        int i = k / NQ, j = k - i * NQ;
        s_nx[k] = qn[j];
        s_ny[k] = qn[i];
        s_nw[k] = qw[i] * qw[j];
    }

    // Per-thread MLP weights in registers
    const int pair = o * CI + c;
    float w1a[HID], w1b[HID], w2[HID][HID], w3[HID];
    {
        const float* p1 = W1g + pair * (2 * HID);
        #pragma unroll
        for (int h = 0; h < HID; h++) { w1a[h] = p1[h]; w1b[h] = p1[HID + h]; }
        const float* p2 = W2g + pair * (HID * HID);
        #pragma unroll
        for (int h = 0; h < HID; h++)
            #pragma unroll
            for (int g = 0; g < HID; g++) w2[h][g] = p2[h * HID + g];
        const float* p3 = W3g + pair * HID;
        #pragma unroll
        for (int g = 0; g < HID; g++) w3[g] = p3[g];
    }

    const float lx = locs[m * 2 + 0];
    const float ly = locs[m * 2 + 1];

    float a0 = 0.0f, a1 = 0.0f;
    __syncthreads();

    for (int k = s; k < KTOT; k += SPLIT) {
        // Bump support test — uniform across the block (depends only on m,k)
        float x0 = lx - s_nx[k];
        float x1 = ly - s_ny[k];
        float r2 = x0 * x0 + x1 * x1;
        float da = DECAYF * r2 * r2;
        if (da >= 1.0f) continue;

        float bump = E_F * __expf(-1.0f / (1.0f - da)) * s_nw[k];

        // Tiny MLP: 2 -> 8 (sin) -> 8 (sin) -> 1
        float h1[HID];
        #pragma unroll
        for (int h = 0; h < HID; h++)
            h1[h] = __sinf(fmaf(x0, w1a[h], x1 * w1b[h]));
        float h2[HID];
        #pragma unroll
        for (int g = 0; g < HID; g++) {
            float acc = 0.0f;
            #pragma unroll
            for (int h = 0; h < HID; h++) acc = fmaf(h1[h], w2[h][g], acc);
            h2[g] = __sinf(acc);
        }
        float val = 0.0f;
        #pragma unroll
        for (int g = 0; g < HID; g++) val = fmaf(h2[g], w3[g], val);
        float v = val * bump;

        // Stage kernel block and feature panel, then rank-update
        __syncthreads();                       // previous iteration's reads done
        s_v[o * 17 + c] = v;
        {
            int t2 = t + 256;
            float f0 = g_featT[k * (BATCH * CI) + t];
            float f1 = g_featT[k * (BATCH * CI) + t2];
            s_f[(t >> 4) * 17 + (t & 15)]   = f0;
            s_f[(t2 >> 4) * 17 + (t2 & 15)] = f1;
        }
        __syncthreads();

        const float* svo = &s_v[o * 17];
        const float* f0p = &s_f[c * 17];
        const float* f1p = &s_f[(c + 16) * 17];
        #pragma unroll
        for (int cc = 0; cc < CI; cc++) {
            float vv = svo[cc];
            a0 = fmaf(vv, f0p[cc], a0);
            a1 = fmaf(vv, f1p[cc], a1);
        }
    }

    // out[b, o, m]; thread (o,c) owns b = c and b = c + 16
    atomicAdd(&out[(c * CO + o) * MTOT + m], a0);
    atomicAdd(&out[((c + 16) * CO + o) * MTOT + m], a1);
}

// ---------------------------------------------------------------------------
extern "C" void kernel_launch(void* const* d_in, const int* in_sizes, int n_in,
                              void* d_out, int out_size) {
    const float* feats = (const float*)d_in[0];  // (32, 16, 576)
    const float* locs  = (const float*)d_in[1];  // (144, 2)
    const float* qn    = (const float*)d_in[2];  // (24,)
    const float* qw    = (const float*)d_in[3];  // (24,)
    const float* W1    = (const float*)d_in[4];  // (16,16,2,8)
    const float* W2    = (const float*)d_in[5];  // (16,16,8,8)
    const float* W3    = (const float*)d_in[6];  // (16,16,8,1)
    float* out = (float*)d_out;                  // (32, 16, 144)

    int prep_work = KTOT * BATCH * CI;           // 294912 (covers out zeroing too)
    qc_prep<<<(prep_work + 255) / 256, 256>>>(feats, out);
    qc_main<<<MTOT * SPLIT, 256>>>(W1, W2, W3, locs, qn, qw, out);
}

// round 3
// speedup vs baseline: 1.4635x; 1.4635x over previous
#include <cuda_runtime.h>

// Shapes (compile-time constants from the reference)
#define NQ     24
#define KTOT   (NQ * NQ)        // 576 quadrature points
#define MSIDE  12
#define MTOT   (MSIDE * MSIDE)  // 144 output locations
#define CI     16
#define CO     16
#define HID    8
#define BATCH  32
#define DECAYF 1296.0f          // (24/4)^4
#define E_F    2.7182818284590452f
#define SPLIT  4                // active-list stripes per m
#define MAXA   128              // max active quad points per output loc (measured ~25 worst)

// Scratch: features transposed to k-major: featT[k*512 + b*16 + c]
__device__ float g_featT[KTOT * BATCH * CI];

// ---------------------------------------------------------------------------
// Prep: zero the output and build featT (features is (B, CI, K) row-major)
// ---------------------------------------------------------------------------
__global__ void qc_prep(const float* __restrict__ feats, float* __restrict__ out) {
    int idx = blockIdx.x * blockDim.x + threadIdx.x;
    if (idx < KTOT * BATCH * CI) {
        int k  = idx >> 9;          // /512
        int bc = idx & 511;         // b*16 + c
        g_featT[idx] = feats[bc * KTOT + k];
    }
    if (idx < BATCH * CO * MTOT) out[idx] = 0.0f;
}

// sin(z) for |z| <= ~0.8 : z - z^3/6 + z^5/120 - z^7/5040, err < 1e-7
__device__ __forceinline__ float sinp(float z) {
    float z2 = z * z;
    float p = fmaf(z2, -1.9841269841e-4f, 8.3333333333e-3f);
    p = fmaf(z2, p, -1.6666666667e-1f);
    p = fmaf(z2, p, 1.0f);
    return z * p;
}

// ---------------------------------------------------------------------------
// Main: one (m, stripe) per block; 256 threads = (o, c) pairs.
// ---------------------------------------------------------------------------
__global__ void __launch_bounds__(256, 2)
qc_main(const float* __restrict__ W1g,   // (CO, CI, 2, 8)
        const float* __restrict__ W2g,   // (CO, CI, 8, 8)
        const float* __restrict__ W3g,   // (CO, CI, 8, 1)
        const float* __restrict__ locs,  // (144, 2)
        const float* __restrict__ qn,    // (24,)
        const float* __restrict__ qw,    // (24,)
        float* __restrict__ out)         // (B, CO, M) — pre-zeroed
{
    const int m = blockIdx.x / SPLIT;
    const int s = blockIdx.x % SPLIT;
    const int t = threadIdx.x;
    const int o = t >> 4;
    const int c = t & 15;

    __shared__ int   s_cnt;
    __shared__ int   s_ak[MAXA];
    __shared__ float s_ax0[MAXA], s_ax1[MAXA], s_abw[MAXA];
    __shared__ float s_v[CO * 17];          // kernel values, padded
    __shared__ float s_f[BATCH * 17];       // feature panel,  padded

    // Per-thread MLP weights in registers (issued first: latency overlaps scan)
    const int pair = o * CI + c;
    float w1a[HID], w1b[HID], w2t[HID][HID], w3[HID];
    {
        const float* p1 = W1g + pair * (2 * HID);
        #pragma unroll
        for (int h = 0; h < HID; h++) { w1a[h] = p1[h]; w1b[h] = p1[HID + h]; }
        const float* p2 = W2g + pair * (HID * HID);
        #pragma unroll
        for (int g = 0; g < HID; g++)
            #pragma unroll
            for (int h = 0; h < HID; h++) w2t[g][h] = p2[h * HID + g];
        const float* p3 = W3g + pair * HID;
        #pragma unroll
        for (int g = 0; g < HID; g++) w3[g] = p3[g];
    }

    // Warp 0: deterministic ballot-compaction of active quad points for this m.
    if (t < 32) {
        const float lx = locs[m * 2 + 0];
        const float ly = locs[m * 2 + 1];
        int cnt = 0;
        for (int base = 0; base < KTOT; base += 32) {     // 576 = 18*32, no tail
            int k = base + t;
            int i = k / NQ, j = k - i * NQ;
            float x0 = lx - qn[j];
            float x1 = ly - qn[i];
            float r2 = x0 * x0 + x1 * x1;
            float da = DECAYF * r2 * r2;
            bool act = (da < 1.0f);
            unsigned bal = __ballot_sync(0xffffffffu, act);
            if (act) {
                int pos = cnt + __popc(bal & ((1u << t) - 1u));
                s_ak[pos]  = k;
                s_ax0[pos] = x0;
                s_ax1[pos] = x1;
                s_abw[pos] = E_F * __expf(-1.0f / (1.0f - da)) * (qw[i] * qw[j]);
            }
            cnt += __popc(bal);
        }
        if (t == 0) s_cnt = cnt;
    }
    __syncthreads();
    const int cnt = s_cnt;

    float a0 = 0.0f, a1 = 0.0f;

    for (int a = s; a < cnt; a += SPLIT) {
        const float x0 = s_ax0[a];
        const float x1 = s_ax1[a];
        const float bw = s_abw[a];
        const int   k  = s_ak[a];

        // Tiny MLP: 2 -> 8 (sin) -> 8 (sin) -> 1, all on the FMA pipe
        float h1[HID];
        #pragma unroll
        for (int h = 0; h < HID; h++)
            h1[h] = sinp(fmaf(x0, w1a[h], x1 * w1b[h]));
        float val = 0.0f;
        #pragma unroll
        for (int g = 0; g < HID; g++) {
            float acc = 0.0f;
            #pragma unroll
            for (int h = 0; h < HID; h++) acc = fmaf(h1[h], w2t[g][h], acc);
            val = fmaf(sinp(acc), w3[g], val);
        }
        float v = val * bw;

        // Stage kernel block and feature panel, then rank-update
        __syncthreads();                       // previous iteration's reads done
        s_v[o * 17 + c] = v;
        {
            int t2 = t + 256;
            float f0 = g_featT[k * (BATCH * CI) + t];
            float f1 = g_featT[k * (BATCH * CI) + t2];
            s_f[(t >> 4) * 17 + (t & 15)]   = f0;
            s_f[(t2 >> 4) * 17 + (t2 & 15)] = f1;
        }
        __syncthreads();

        const float* svo = &s_v[o * 17];
        const float* f0p = &s_f[c * 17];
        const float* f1p = &s_f[(c + 16) * 17];
        #pragma unroll
        for (int cc = 0; cc < CI; cc++) {
            float vv = svo[cc];
            a0 = fmaf(vv, f0p[cc], a0);
            a1 = fmaf(vv, f1p[cc], a1);
        }
    }

    // out[b, o, m]; thread (o,c) owns b = c and b = c + 16
    atomicAdd(&out[(c * CO + o) * MTOT + m], a0);
    atomicAdd(&out[((c + 16) * CO + o) * MTOT + m], a1);
}

// ---------------------------------------------------------------------------
extern "C" void kernel_launch(void* const* d_in, const int* in_sizes, int n_in,
                              void* d_out, int out_size) {
    const float* feats = (const float*)d_in[0];  // (32, 16, 576)
    const float* locs  = (const float*)d_in[1];  // (144, 2)
    const float* qn    = (const float*)d_in[2];  // (24,)
    const float* qw    = (const float*)d_in[3];  // (24,)
    const float* W1    = (const float*)d_in[4];  // (16,16,2,8)
    const float* W2    = (const float*)d_in[5];  // (16,16,8,8)
    const float* W3    = (const float*)d_in[6];  // (16,16,8,1)
    float* out = (float*)d_out;                  // (32, 16, 144)

    int prep_work = KTOT * BATCH * CI;           // 294912 (covers out zeroing too)
    qc_prep<<<(prep_work + 255) / 256, 256>>>(feats, out);
    qc_main<<<MTOT * SPLIT, 256>>>(W1, W2, W3, locs, qn, qw, out);
}

// round 4
// speedup vs baseline: 2.8761x; 1.9652x over previous
#include <cuda_runtime.h>

#define NQ     24
#define KTOT   (NQ * NQ)        // 576 quadrature points
#define MSIDE  12
#define MTOT   (MSIDE * MSIDE)  // 144 output locations
#define CI     16
#define CO     16
#define HID    8
#define BATCH  32
#define DECAYF 1296.0f          // (24/4)^4
#define E_F    2.7182818284590452f
#define SPLIT  4                // active-list stripes per m
#define MAXA   128              // max active quad points per output loc (~30 measured worst)
#define MAXPB  (MAXA / SPLIT)   // max active points handled per block (32)
#define NW     88               // weights per (o,c) pair: 16 (W1) + 64 (W2) + 8 (W3)

// Scratch
__device__ float g_featT[KTOT * BATCH * CI];   // featT[k*512 + b*16 + c]
__device__ float g_Wt[NW * 256];               // Wt[w*256 + pair]  (pair-coalesced)

// ---------------------------------------------------------------------------
// Prep: zero out, transpose features to k-major, transpose weights to
// pair-minor so the main kernel's weight loads are fully coalesced.
// ---------------------------------------------------------------------------
__global__ void qc_prep(const float* __restrict__ feats,
                        const float* __restrict__ W1,
                        const float* __restrict__ W2,
                        const float* __restrict__ W3,
                        float* __restrict__ out) {
    int idx = blockIdx.x * blockDim.x + threadIdx.x;
    if (idx < KTOT * BATCH * CI) {
        int k  = idx >> 9;          // /512
        int bc = idx & 511;         // b*16 + c
        g_featT[idx] = feats[bc * KTOT + k];
    }
    if (idx < NW * 256) {
        int w = idx >> 8, pair = idx & 255;
        float v;
        if (w < 16) {                      // w1a[h]=W1[p][0][h] (w<8), w1b[h]=W1[p][1][h]
            v = W1[pair * 16 + w];
        } else if (w < 80) {               // w2t[g][h] = W2[p][h][g]
            int r = w - 16, g = r >> 3, h = r & 7;
            v = W2[pair * 64 + h * 8 + g];
        } else {                           // w3[g]
            v = W3[pair * 8 + (w - 80)];
        }
        g_Wt[idx] = v;
    }
    if (idx < BATCH * CO * MTOT) out[idx] = 0.0f;
}

// sin(z) for |z| <= ~0.8 : z - z^3/6 + z^5/120 - z^7/5040, err < 1e-7
__device__ __forceinline__ float sinp(float z) {
    float z2 = z * z;
    float p = fmaf(z2, -1.9841269841e-4f, 8.3333333333e-3f);
    p = fmaf(z2, p, -1.6666666667e-1f);
    p = fmaf(z2, p, 1.0f);
    return z * p;
}

// ---------------------------------------------------------------------------
// Main: one (m, stripe) per block; 256 threads = (o, c) pairs.
// ---------------------------------------------------------------------------
__global__ void __launch_bounds__(256, 2)
qc_main(const float* __restrict__ locs,  // (144, 2)
        const float* __restrict__ qn,    // (24,)
        const float* __restrict__ qw,    // (24,)
        float* __restrict__ out)         // (B, CO, M) — pre-zeroed
{
    const int m = blockIdx.x / SPLIT;
    const int s = blockIdx.x % SPLIT;
    const int t = threadIdx.x;
    const int o = t >> 4;
    const int c = t & 15;

    __shared__ int   s_cnt;
    __shared__ int   s_ak[MAXA];
    __shared__ float s_ax0[MAXA], s_ax1[MAXA], s_abw[MAXA];
    __shared__ float s_vall[MAXPB * 256];   // kernel values per (iter, pair)

    // Coalesced per-thread weight loads (lane == pair within each warp row)
    float w1a[HID], w1b[HID], w2t[HID][HID], w3[HID];
    {
        const float* W = g_Wt + t;
        #pragma unroll
        for (int h = 0; h < HID; h++) { w1a[h] = W[h * 256]; w1b[h] = W[(8 + h) * 256]; }
        #pragma unroll
        for (int g = 0; g < HID; g++)
            #pragma unroll
            for (int h = 0; h < HID; h++) w2t[g][h] = W[(16 + g * 8 + h) * 256];
        #pragma unroll
        for (int g = 0; g < HID; g++) w3[g] = W[(80 + g) * 256];
    }

    // Warp 0: deterministic ballot-compaction of active quad points for this m.
    if (t < 32) {
        const float lx = locs[m * 2 + 0];
        const float ly = locs[m * 2 + 1];
        int cnt = 0;
        for (int base = 0; base < KTOT; base += 32) {     // 576 = 18*32, no tail
            int k = base + t;
            int i = k / NQ, j = k - i * NQ;
            float x0 = lx - qn[j];
            float x1 = ly - qn[i];
            float r2 = x0 * x0 + x1 * x1;
            float da = DECAYF * r2 * r2;
            bool act = (da < 1.0f);
            unsigned bal = __ballot_sync(0xffffffffu, act);
            if (act) {
                int pos = cnt + __popc(bal & ((1u << t) - 1u));
                s_ak[pos]  = k;
                s_ax0[pos] = x0;
                s_ax1[pos] = x1;
                s_abw[pos] = E_F * __expf(-1.0f / (1.0f - da)) * (qw[i] * qw[j]);
            }
            cnt += __popc(bal);
        }
        if (t == 0) s_cnt = cnt;
    }
    __syncthreads();
    const int cnt = s_cnt;

    // Phase 1: evaluate all kernel values for this block (no barriers inside)
    {
        int ai = 0;
        for (int a = s; a < cnt; a += SPLIT, ai++) {
            const float x0 = s_ax0[a];
            const float x1 = s_ax1[a];
            const float bw = s_abw[a];

            float h1[HID];
            #pragma unroll
            for (int h = 0; h < HID; h++)
                h1[h] = sinp(fmaf(x0, w1a[h], x1 * w1b[h]));
            float val = 0.0f;
            #pragma unroll
            for (int g = 0; g < HID; g++) {
                float acc = 0.0f;
                #pragma unroll
                for (int h = 0; h < HID; h++) acc = fmaf(h1[h], w2t[g][h], acc);
                val = fmaf(sinp(acc), w3[g], val);
            }
            s_vall[ai * 256 + t] = val * bw;
        }
    }
    __syncthreads();

    // Phase 2: contraction. Features read directly (coalesced float4 panels).
    float a0 = 0.0f, a1 = 0.0f;
    {
        int ai = 0;
        for (int a = s; a < cnt; a += SPLIT, ai++) {
            const int k = s_ak[a];
            const float* svo = &s_vall[ai * 256 + o * 16];
            const float4* f0 = (const float4*)(g_featT + k * (BATCH * CI) + c * 16);
            const float4* f1 = (const float4*)(g_featT + k * (BATCH * CI) + (c + 16) * 16);
            #pragma unroll
            for (int q = 0; q < 4; q++) {
                float4 fa = f0[q];
                float4 fb = f1[q];
                float v0 = svo[q * 4 + 0], v1 = svo[q * 4 + 1];
                float v2 = svo[q * 4 + 2], v3 = svo[q * 4 + 3];
                a0 = fmaf(v0, fa.x, a0); a1 = fmaf(v0, fb.x, a1);
                a0 = fmaf(v1, fa.y, a0); a1 = fmaf(v1, fb.y, a1);
                a0 = fmaf(v2, fa.z, a0); a1 = fmaf(v2, fb.z, a1);
                a0 = fmaf(v3, fa.w, a0); a1 = fmaf(v3, fb.w, a1);
            }
        }
    }

    // out[b, o, m]; thread (o,c) owns b = c and b = c + 16
    atomicAdd(&out[(c * CO + o) * MTOT + m], a0);
    atomicAdd(&out[((c + 16) * CO + o) * MTOT + m], a1);
}

// ---------------------------------------------------------------------------
extern "C" void kernel_launch(void* const* d_in, const int* in_sizes, int n_in,
                              void* d_out, int out_size) {
    const float* feats = (const float*)d_in[0];  // (32, 16, 576)
    const float* locs  = (const float*)d_in[1];  // (144, 2)
    const float* qn    = (const float*)d_in[2];  // (24,)
    const float* qw    = (const float*)d_in[3];  // (24,)
    const float* W1    = (const float*)d_in[4];  // (16,16,2,8)
    const float* W2    = (const float*)d_in[5];  // (16,16,8,8)
    const float* W3    = (const float*)d_in[6];  // (16,16,8,1)
    float* out = (float*)d_out;                  // (32, 16, 144)

    int prep_work = KTOT * BATCH * CI;           // 294912 (covers Wt + out too)
    qc_prep<<<(prep_work + 255) / 256, 256>>>(feats, W1, W2, W3, out);
    qc_main<<<MTOT * SPLIT, 256>>>(locs, qn, qw, out);
}

// round 5
// speedup vs baseline: 4.4027x; 1.5308x over previous
#include <cuda_runtime.h>

#define NQ      24
#define KTOT    576
#define MSIDE   12
#define MTOT    144
#define CI      16
#define CO      16
#define HID     8
#define BATCH   32
#define DECAYF  1296.0f
#define E_F     2.7182818284590452f
#define NW      88            // weights per pair: 16 + 64 + 8
#define PSTRIDE 64            // padded per-m slots in the active-point list
#define NB      296           // main grid: one wave at 2 blocks/SM
#define PREP_B  1152          // transpose/zero blocks in prep

// Scratch
__device__ float  g_featT2[KTOT * BATCH * CI];  // [k][c][b] : feat[b,c,k]
__device__ float  g_Wt[NW * 256];               // [w][pair]  coalesced weights
__device__ float4 g_pts[MTOT * PSTRIDE];        // (x0, x1, bump*w, k-as-int)
__device__ int    g_cnt[MTOT];                  // active count per m

// ---------------------------------------------------------------------------
// Prep: blocks [0,PREP_B) transpose features + weights and zero out;
// blocks [PREP_B, PREP_B+144) build the per-m active-point lists.
// ---------------------------------------------------------------------------
__global__ void qc_prep(const float* __restrict__ feats,
                        const float* __restrict__ W1,
                        const float* __restrict__ W2,
                        const float* __restrict__ W3,
                        const float* __restrict__ locs,
                        const float* __restrict__ qn,
                        const float* __restrict__ qw,
                        float* __restrict__ out) {
    if (blockIdx.x < PREP_B) {
        int idx = blockIdx.x * 256 + threadIdx.x;
        if (idx < KTOT * BATCH * CI) {              // featT2[k*512 + c*32 + b]
            int k = idx >> 9, r = idx & 511, c = r >> 5, b = r & 31;
            g_featT2[idx] = feats[(b * CI + c) * KTOT + k];
        }
        if (idx < NW * 256) {
            int w = idx >> 8, pair = idx & 255;
            float v;
            if (w < 16)      v = W1[pair * 16 + w];               // w1a(8) then w1b(8)
            else if (w < 80) { int r = w - 16, g = r >> 3, h = r & 7;
                               v = W2[pair * 64 + h * 8 + g]; }   // transposed
            else             v = W3[pair * 8 + (w - 80)];
            g_Wt[idx] = v;
        }
        if (idx < BATCH * CO * MTOT) out[idx] = 0.0f;
    } else {
        // Per-m active scan (warp 0 of each scan block, deterministic order)
        int m = blockIdx.x - PREP_B;
        int t = threadIdx.x;
        if (t < 32) {
            const float lx = locs[m * 2 + 0];
            const float ly = locs[m * 2 + 1];
            int cnt = 0;
            for (int base = 0; base < KTOT; base += 32) {   // 576 = 18*32
                int k = base + t;
                int i = k / NQ, j = k - i * NQ;
                float x0 = lx - qn[j];
                float x1 = ly - qn[i];
                float r2 = x0 * x0 + x1 * x1;
                float da = DECAYF * r2 * r2;
                bool act = (da < 1.0f);
                unsigned bal = __ballot_sync(0xffffffffu, act);
                if (act) {
                    int pos = cnt + __popc(bal & ((1u << t) - 1u));
                    float bw = E_F * __expf(-1.0f / (1.0f - da)) * (qw[i] * qw[j]);
                    g_pts[m * PSTRIDE + pos] = make_float4(x0, x1, bw, __int_as_float(k));
                }
                cnt += __popc(bal);
            }
            if (t == 0) g_cnt[m] = cnt;
        }
    }
}

// sin(z) for |z| <= ~0.7 : z - z^3/6 + z^5/120  (abs err < 2e-5)
__device__ __forceinline__ float sinp(float z) {
    float z2 = z * z;
    float p = fmaf(z2, 8.3333333e-3f, -1.6666667e-1f);
    return z * fmaf(z2, p, 1.0f);
}

// ---------------------------------------------------------------------------
// Main: NB blocks, each takes an equal contiguous chunk of the flat active
// list. 256 threads: MLP as pair (o, c=t&15); contraction as (o, bhat=t&15)
// owning batches b = 2*bhat, 2*bhat+1. No barriers in the main loop.
// ---------------------------------------------------------------------------
__global__ void __launch_bounds__(256, 2)
qc_main(float* __restrict__ out) {
    const int t    = threadIdx.x;
    const int lane = t & 31;
    const int o    = t >> 4;
    const int bh   = t & 15;

    __shared__ int s_off[MTOT + 1];   // exclusive prefix of g_cnt

    // Coalesced per-thread weight loads
    float w1a[HID], w1b[HID], w2t[HID][HID], w3[HID];
    {
        const float* W = g_Wt + t;
        #pragma unroll
        for (int h = 0; h < HID; h++) { w1a[h] = W[h * 256]; w1b[h] = W[(8 + h) * 256]; }
        #pragma unroll
        for (int g = 0; g < HID; g++)
            #pragma unroll
            for (int h = 0; h < HID; h++) w2t[g][h] = W[(16 + g * 8 + h) * 256];
        #pragma unroll
        for (int g = 0; g < HID; g++) w3[g] = W[(80 + g) * 256];
    }

    // Warp 0: exclusive prefix over 144 counts (5 per lane + warp scan)
    if (t < 32) {
        int base = t * 5;
        int c0 = (base + 0 < MTOT) ? g_cnt[base + 0] : 0;
        int c1 = (base + 1 < MTOT) ? g_cnt[base + 1] : 0;
        int c2 = (base + 2 < MTOT) ? g_cnt[base + 2] : 0;
        int c3 = (base + 3 < MTOT) ? g_cnt[base + 3] : 0;
        int c4 = (base + 4 < MTOT) ? g_cnt[base + 4] : 0;
        int l0 = c0, l1 = l0 + c1, l2 = l1 + c2, l3 = l2 + c3, l4 = l3 + c4;
        int x = l4;
        #pragma unroll
        for (int d = 1; d < 32; d <<= 1) {
            int y = __shfl_up_sync(0xffffffffu, x, d);
            if (lane >= d) x += y;
        }
        int excl = x - l4;
        if (base + 0 <= MTOT) s_off[base + 0] = excl;
        if (base + 1 <= MTOT) s_off[base + 1] = excl + l0;
        if (base + 2 <= MTOT) s_off[base + 2] = excl + l1;
        if (base + 3 <= MTOT) s_off[base + 3] = excl + l2;
        if (base + 4 <= MTOT) s_off[base + 4] = excl + l3;
    }
    __syncthreads();

    const int T = s_off[MTOT];
    const int chunk = (T + NB - 1) / NB;
    int p0 = blockIdx.x * chunk;
    int p1 = min(p0 + chunk, T);
    if (p0 >= p1) return;

    // Binary search: largest m with s_off[m] <= p0
    int lo = 0, hi = MTOT;
    while (hi - lo > 1) { int mid = (lo + hi) >> 1; (s_off[mid] <= p0) ? (lo = mid) : (hi = mid); }
    int m = lo;
    int ibase = s_off[m], inext = s_off[m + 1];

    float a0 = 0.0f, a1 = 0.0f;

    for (int p = p0; p < p1; p++) {
        if (p >= inext) {
            atomicAdd(&out[(2 * bh)     * (CO * MTOT) + o * MTOT + m], a0);
            atomicAdd(&out[(2 * bh + 1) * (CO * MTOT) + o * MTOT + m], a1);
            a0 = 0.0f; a1 = 0.0f;
            do { m++; } while (p >= s_off[m + 1]);
            ibase = s_off[m]; inext = s_off[m + 1];
        }
        float4 pt = g_pts[m * PSTRIDE + (p - ibase)];
        float x0 = pt.x, x1 = pt.y, bw = pt.z;
        int   k  = __float_as_int(pt.w);

        // Tiny MLP: 2 -> 8 (sin) -> 8 (sin) -> 1 (all FMA pipe)
        float h1[HID];
        #pragma unroll
        for (int h = 0; h < HID; h++)
            h1[h] = sinp(fmaf(x0, w1a[h], x1 * w1b[h]));
        float val = 0.0f;
        #pragma unroll
        for (int g = 0; g < HID; g++) {
            float acc = 0.0f;
            #pragma unroll
            for (int h = 0; h < HID; h++) acc = fmaf(h1[h], w2t[g][h], acc);
            val = fmaf(sinp(acc), w3[g], val);
        }
        float v = val * bw;

        // Contraction: v[o,cc] via intra-warp shuffle, features b-major float2
        const float* fb = g_featT2 + k * (BATCH * CI) + 2 * bh;
        #pragma unroll
        for (int cc = 0; cc < CI; cc++) {
            float vv = __shfl_sync(0xffffffffu, v, (lane & 16) + cc);
            float2 f = *(const float2*)(fb + cc * 32);
            a0 = fmaf(vv, f.x, a0);
            a1 = fmaf(vv, f.y, a1);
        }
    }
    atomicAdd(&out[(2 * bh)     * (CO * MTOT) + o * MTOT + m], a0);
    atomicAdd(&out[(2 * bh + 1) * (CO * MTOT) + o * MTOT + m], a1);
}

// ---------------------------------------------------------------------------
extern "C" void kernel_launch(void* const* d_in, const int* in_sizes, int n_in,
                              void* d_out, int out_size) {
    const float* feats = (const float*)d_in[0];  // (32, 16, 576)
    const float* locs  = (const float*)d_in[1];  // (144, 2)
    const float* qn    = (const float*)d_in[2];  // (24,)
    const float* qw    = (const float*)d_in[3];  // (24,)
    const float* W1    = (const float*)d_in[4];  // (16,16,2,8)
    const float* W2    = (const float*)d_in[5];  // (16,16,8,8)
    const float* W3    = (const float*)d_in[6];  // (16,16,8,1)
    float* out = (float*)d_out;                  // (32, 16, 144)

    qc_prep<<<PREP_B + MTOT, 256>>>(feats, W1, W2, W3, locs, qn, qw, out);
    qc_main<<<NB, 256>>>(out);
}

// round 7
// speedup vs baseline: 4.4696x; 1.0152x over previous
#include <cuda_runtime.h>
#include <cstdint>

#define NQ      24
#define KTOT    576
#define MSIDE   12
#define MTOT    144
#define CI      16
#define CO      16
#define HID     8
#define BATCH   32
#define DECAYF  1296.0f
#define E_F     2.7182818284590452f
#define NW      88            // weights per pair: 16 + 64 + 8
#define PSTRIDE 64            // padded per-m slots in the active-point list
#define NB      296           // main grid: one wave at 2 blocks/SM
#define PREP_B  1152

// Scratch
__device__ float  g_featT2[KTOT * BATCH * CI];  // [k][c][b] : feat[b,c,k]
__device__ float  g_Wt[NW * 256];               // [w][pair]  coalesced weights
__device__ float4 g_pts[MTOT * PSTRIDE];        // (x0, x1, bump*w, k-as-int)
__device__ int    g_cnt[MTOT];

// ---------------------------------------------------------------------------
__global__ void qc_prep(const float* __restrict__ feats,
                        const float* __restrict__ W1,
                        const float* __restrict__ W2,
                        const float* __restrict__ W3,
                        const float* __restrict__ locs,
                        const float* __restrict__ qn,
                        const float* __restrict__ qw,
                        float* __restrict__ out) {
    if (blockIdx.x < PREP_B) {
        int idx = blockIdx.x * 256 + threadIdx.x;
        if (idx < KTOT * BATCH * CI) {              // featT2[k*512 + c*32 + b]
            int k = idx >> 9, r = idx & 511, c = r >> 5, b = r & 31;
            g_featT2[idx] = feats[(b * CI + c) * KTOT + k];
        }
        if (idx < NW * 256) {
            int w = idx >> 8, pair = idx & 255;
            float v;
            if (w < 16)      v = W1[pair * 16 + w];
            else if (w < 80) { int r = w - 16, g = r >> 3, h = r & 7;
                               v = W2[pair * 64 + h * 8 + g]; }
            else             v = W3[pair * 8 + (w - 80)];
            g_Wt[idx] = v;
        }
        if (idx < BATCH * CO * MTOT) out[idx] = 0.0f;
    } else {
        int m = blockIdx.x - PREP_B;
        int t = threadIdx.x;
        if (t < 32) {
            const float lx = locs[m * 2 + 0];
            const float ly = locs[m * 2 + 1];
            int cnt = 0;
            for (int base = 0; base < KTOT; base += 32) {   // 576 = 18*32
                int k = base + t;
                int i = k / NQ, j = k - i * NQ;
                float x0 = lx - qn[j];
                float x1 = ly - qn[i];
                float r2 = x0 * x0 + x1 * x1;
                float da = DECAYF * r2 * r2;
                bool act = (da < 1.0f);
                unsigned bal = __ballot_sync(0xffffffffu, act);
                if (act) {
                    int pos = cnt + __popc(bal & ((1u << t) - 1u));
                    float bw = E_F * __expf(-1.0f / (1.0f - da)) * (qw[i] * qw[j]);
                    g_pts[m * PSTRIDE + pos] = make_float4(x0, x1, bw, __int_as_float(k));
                }
                cnt += __popc(bal);
            }
            if (t == 0) g_cnt[m] = cnt;
        }
    }
}

// sin(z) for |z| <= ~0.7 : z - z^3/6 + z^5/120  (abs err < 2e-5)
__device__ __forceinline__ float sinp(float z) {
    float z2 = z * z;
    float p = fmaf(z2, 8.3333333e-3f, -1.6666667e-1f);
    return z * fmaf(z2, p, 1.0f);
}

__device__ __forceinline__ void cp8(uint32_t dst_smem, const void* src) {
    asm volatile("cp.async.ca.shared.global [%0], [%1], 8;\n"
                 :: "r"(dst_smem), "l"(src) : "memory");
}
#define CP_COMMIT() asm volatile("cp.async.commit_group;\n" ::: "memory")
#define CP_WAIT1()  asm volatile("cp.async.wait_group 1;\n" ::: "memory")

// ---------------------------------------------------------------------------
// Main: flat active-list chunks; double-buffered smem feature panels loaded
// via cp.async two points ahead; contraction from smem; no LDG in hot loop.
// ---------------------------------------------------------------------------
__global__ void __launch_bounds__(256, 2)
qc_main(float* __restrict__ out) {
    const int t    = threadIdx.x;
    const int lane = t & 31;
    const int o    = t >> 4;
    const int bh   = t & 15;

    // 16B-aligned and declared FIRST: cp.async 8B and float2 LDS need >=8B
    // alignment (this was the round-6 misaligned-address bug).
    __shared__ __align__(16) float s_f[2][BATCH * CI];  // 2x 2KB feature panels
    __shared__ int s_off[MTOT + 1];

    // Coalesced per-thread weight loads
    float w1a[HID], w1b[HID], w2t[HID][HID], w3[HID];
    {
        const float* W = g_Wt + t;
        #pragma unroll
        for (int h = 0; h < HID; h++) { w1a[h] = W[h * 256]; w1b[h] = W[(8 + h) * 256]; }
        #pragma unroll
        for (int g = 0; g < HID; g++)
            #pragma unroll
            for (int h = 0; h < HID; h++) w2t[g][h] = W[(16 + g * 8 + h) * 256];
        #pragma unroll
        for (int g = 0; g < HID; g++) w3[g] = W[(80 + g) * 256];
    }

    // Warp 0: exclusive prefix over 144 counts
    if (t < 32) {
        int base = t * 5;
        int c0 = (base + 0 < MTOT) ? g_cnt[base + 0] : 0;
        int c1 = (base + 1 < MTOT) ? g_cnt[base + 1] : 0;
        int c2 = (base + 2 < MTOT) ? g_cnt[base + 2] : 0;
        int c3 = (base + 3 < MTOT) ? g_cnt[base + 3] : 0;
        int c4 = (base + 4 < MTOT) ? g_cnt[base + 4] : 0;
        int l0 = c0, l1 = l0 + c1, l2 = l1 + c2, l3 = l2 + c3, l4 = l3 + c4;
        int x = l4;
        #pragma unroll
        for (int d = 1; d < 32; d <<= 1) {
            int y = __shfl_up_sync(0xffffffffu, x, d);
            if (lane >= d) x += y;
        }
        int excl = x - l4;
        if (base + 0 <= MTOT) s_off[base + 0] = excl;
        if (base + 1 <= MTOT) s_off[base + 1] = excl + l0;
        if (base + 2 <= MTOT) s_off[base + 2] = excl + l1;
        if (base + 3 <= MTOT) s_off[base + 3] = excl + l2;
        if (base + 4 <= MTOT) s_off[base + 4] = excl + l3;
    }
    __syncthreads();

    const int T = s_off[MTOT];
    const int chunk = (T + NB - 1) / NB;
    const int p0 = blockIdx.x * chunk;
    const int p1 = min(p0 + chunk, T);
    if (p0 >= p1) return;

    // Binary search: largest m with s_off[m] <= p0
    int lo = 0, hi = MTOT;
    while (hi - lo > 1) { int mid = (lo + hi) >> 1; (s_off[mid] <= p0) ? (lo = mid) : (hi = mid); }

    // Compute cursor (output flush) and fetch cursor (prefetch lookahead)
    int cm = lo, cnext = s_off[cm + 1];
    int fm = lo, fbase = s_off[fm], fnext = s_off[fm + 1];

    const uint32_t sfb = (uint32_t)__cvta_generic_to_shared(&s_f[0][0]);
    const uint32_t myoff = (uint32_t)(t * 8);

    float4 q[2];
    // Prefetch points p0 and p0+1
    {
        while (p0 >= fnext) { fm++; fbase = s_off[fm]; fnext = s_off[fm + 1]; }
        q[0] = g_pts[fm * PSTRIDE + (p0 - fbase)];
        cp8(sfb + myoff, g_featT2 + (size_t)__float_as_int(q[0].w) * 512 + t * 2);
        CP_COMMIT();
        if (p0 + 1 < p1) {
            while (p0 + 1 >= fnext) { fm++; fbase = s_off[fm]; fnext = s_off[fm + 1]; }
            q[1] = g_pts[fm * PSTRIDE + (p0 + 1 - fbase)];
            cp8(sfb + 2048 + myoff, g_featT2 + (size_t)__float_as_int(q[1].w) * 512 + t * 2);
        }
        CP_COMMIT();
    }

    float a0 = 0.0f, a1 = 0.0f;

    for (int p = p0; p < p1; p++) {
        const int buf = (p - p0) & 1;
        const float4 pt = q[buf];
        const float x0 = pt.x, x1 = pt.y, bw = pt.z;

        if (p >= cnext) {   // m advanced: flush partials
            atomicAdd(&out[(2 * bh)     * (CO * MTOT) + o * MTOT + cm], a0);
            atomicAdd(&out[(2 * bh + 1) * (CO * MTOT) + o * MTOT + cm], a1);
            a0 = 0.0f; a1 = 0.0f;
            do { cm++; } while (p >= s_off[cm + 1]);
            cnext = s_off[cm + 1];
        }

        // Tiny MLP: 2 -> 8 (sin) -> 8 (sin) -> 1 (all FMA pipe)
        float h1[HID];
        #pragma unroll
        for (int h = 0; h < HID; h++)
            h1[h] = sinp(fmaf(x0, w1a[h], x1 * w1b[h]));
        float val = 0.0f;
        #pragma unroll
        for (int g = 0; g < HID; g++) {
            float acc = 0.0f;
            #pragma unroll
            for (int h = 0; h < HID; h++) acc = fmaf(h1[h], w2t[g][h], acc);
            val = fmaf(sinp(acc), w3[g], val);
        }
        float v = val * bw;

        // Panel for p is the older of <=2 pending groups
        CP_WAIT1();
        __syncthreads();

        // Contraction: v[o,cc] via shfl, features from smem panel
        const float* fb = &s_f[buf][2 * bh];
        #pragma unroll
        for (int cc = 0; cc < CI; cc++) {
            float vv = __shfl_sync(0xffffffffu, v, (lane & 16) + cc);
            float2 f = *(const float2*)(fb + cc * 32);
            a0 = fmaf(vv, f.x, a0);
            a1 = fmaf(vv, f.y, a1);
        }
        __syncthreads();   // reads of this buffer done; safe to overwrite

        // Prefetch p+2 into the buffer just freed
        if (p + 2 < p1) {
            while (p + 2 >= fnext) { fm++; fbase = s_off[fm]; fnext = s_off[fm + 1]; }
            q[buf] = g_pts[fm * PSTRIDE + (p + 2 - fbase)];
            cp8(sfb + (uint32_t)buf * 2048 + myoff,
                g_featT2 + (size_t)__float_as_int(q[buf].w) * 512 + t * 2);
        }
        CP_COMMIT();
    }

    atomicAdd(&out[(2 * bh)     * (CO * MTOT) + o * MTOT + cm], a0);
    atomicAdd(&out[(2 * bh + 1) * (CO * MTOT) + o * MTOT + cm], a1);
}

// ---------------------------------------------------------------------------
extern "C" void kernel_launch(void* const* d_in, const int* in_sizes, int n_in,
                              void* d_out, int out_size) {
    const float* feats = (const float*)d_in[0];  // (32, 16, 576)
    const float* locs  = (const float*)d_in[1];  // (144, 2)
    const float* qn    = (const float*)d_in[2];  // (24,)
    const float* qw    = (const float*)d_in[3];  // (24,)
    const float* W1    = (const float*)d_in[4];  // (16,16,2,8)
    const float* W2    = (const float*)d_in[5];  // (16,16,8,8)
    const float* W3    = (const float*)d_in[6];  // (16,16,8,1)
    float* out = (float*)d_out;                  // (32, 16, 144)

    qc_prep<<<PREP_B + MTOT, 256>>>(feats, W1, W2, W3, locs, qn, qw, out);
    qc_main<<<NB, 256>>>(out);
}

// round 8
// speedup vs baseline: 5.4669x; 1.2231x over previous
#include <cuda_runtime.h>
#include <cstdint>

#define NQ      24
#define KTOT    576
#define MSIDE   12
#define MTOT    144
#define CI      16
#define CO      16
#define HID     8
#define BATCH   32
#define DECAYF  1296.0f
#define E_F     2.7182818284590452f
#define NW      88            // weights per pair: 16 + 64 + 8
#define PSTRIDE 64            // padded per-m slots in the active-point list
#define NB      296           // main grid: one wave at 2 blocks/SM
#define MAXC    32            // max points per block (chunk bound; T<=9216)

// prep block ranges
#define PB_TR   288           // transpose: 16 c * 18 k-tiles
#define PB_SCAN (PB_TR + MTOT)        // 288..432
#define PB_W    (PB_SCAN + NW)        // 432..520 weight blocks
#define PB_Z    (PB_W + 72)           // 520..592 zero blocks

// Scratch
__device__ float  g_featT2[KTOT * BATCH * CI];  // [k][c*32+b]
__device__ float  g_Wt[NW * 256];               // [w][pair]
__device__ float4 g_pts[MTOT * PSTRIDE];        // (x0, x1, bump*w, k-as-int)
__device__ int    g_cnt[MTOT];

// ---------------------------------------------------------------------------
// Prep: coalesced tiled transpose + scan + weight pack + out zero.
// ---------------------------------------------------------------------------
__global__ void qc_prep(const float* __restrict__ feats,
                        const float* __restrict__ W1,
                        const float* __restrict__ W2,
                        const float* __restrict__ W3,
                        const float* __restrict__ locs,
                        const float* __restrict__ qn,
                        const float* __restrict__ qw,
                        float* __restrict__ out) {
    const int bid = blockIdx.x;
    const int t = threadIdx.x;
    if (bid < PB_TR) {
        // Transpose one (c, k-tile) plane: in[b][k0+kk] -> featT2[k0+kk][c*32+b]
        __shared__ float tile[32][33];
        const int c  = bid & 15;
        const int k0 = (bid >> 4) * 32;
        const int x  = t & 31;           // kk on read, b on write
        const int y0 = t >> 5;           // 8 rows per pass
        #pragma unroll
        for (int y = y0; y < 32; y += 8)                   // y = b
            tile[y][x] = feats[(y * CI + c) * KTOT + k0 + x];
        __syncthreads();
        #pragma unroll
        for (int y = y0; y < 32; y += 8)                   // y = kk
            g_featT2[(k0 + y) * 512 + c * 32 + x] = tile[x][y];
    } else if (bid < PB_SCAN) {
        // Per-m active scan (warp 0, deterministic ballot compaction)
        const int m = bid - PB_TR;
        if (t < 32) {
            const float lx = locs[m * 2 + 0];
            const float ly = locs[m * 2 + 1];
            int cnt = 0;
            for (int base = 0; base < KTOT; base += 32) {   // 576 = 18*32
                int k = base + t;
                int i = k / NQ, j = k - i * NQ;
                float x0 = lx - qn[j];
                float x1 = ly - qn[i];
                float r2 = x0 * x0 + x1 * x1;
                float da = DECAYF * r2 * r2;
                bool act = (da < 1.0f);
                unsigned bal = __ballot_sync(0xffffffffu, act);
                if (act) {
                    int pos = cnt + __popc(bal & ((1u << t) - 1u));
                    float bw = E_F * __expf(-1.0f / (1.0f - da)) * (qw[i] * qw[j]);
                    g_pts[m * PSTRIDE + pos] = make_float4(x0, x1, bw, __int_as_float(k));
                }
                cnt += __popc(bal);
            }
            if (t == 0) g_cnt[m] = cnt;
        }
    } else if (bid < PB_W) {
        // Weight pack: g_Wt[w][pair]
        const int w = bid - PB_SCAN;
        const int pair = t;
        float v;
        if (w < 16)      v = W1[pair * 16 + w];
        else if (w < 80) { int r = w - 16, g = r >> 3, h = r & 7;
                           v = W2[pair * 64 + h * 8 + g]; }
        else             v = W3[pair * 8 + (w - 80)];
        g_Wt[w * 256 + pair] = v;
    } else if (bid < PB_Z) {
        int idx = (bid - PB_W) * 256 + t;                  // 18432 float4 slots
        ((float4*)out)[idx] = make_float4(0.f, 0.f, 0.f, 0.f);
    }
}

__device__ __forceinline__ void cp8(uint32_t dst_smem, const void* src) {
    asm volatile("cp.async.ca.shared.global [%0], [%1], 8;\n"
                 :: "r"(dst_smem), "l"(src) : "memory");
}
#define CP_COMMIT() asm volatile("cp.async.commit_group;\n" ::: "memory")
#define CP_WAIT3()  asm volatile("cp.async.wait_group 3;\n" ::: "memory")

// ---------------------------------------------------------------------------
// Main: flat active-list chunks; point metadata preloaded to smem; 4-deep
// cp.async feature pipeline; sins on MUFU; contraction via shfl + smem.
// ---------------------------------------------------------------------------
__global__ void __launch_bounds__(256, 2)
qc_main(float* __restrict__ out) {
    const int t    = threadIdx.x;
    const int lane = t & 31;
    const int o    = t >> 4;
    const int bh   = t & 15;

    __shared__ __align__(16) float s_f[4][BATCH * CI];   // 4x 2KB feature panels
    __shared__ __align__(16) float4 s_pts[MAXC];
    __shared__ int s_pm[MAXC];
    __shared__ int s_off[MTOT + 1];

    // Coalesced per-thread weight loads (lane == pair)
    float w1a[HID], w1b[HID], w2t[HID][HID], w3[HID];
    {
        const float* W = g_Wt + t;
        #pragma unroll
        for (int h = 0; h < HID; h++) { w1a[h] = W[h * 256]; w1b[h] = W[(8 + h) * 256]; }
        #pragma unroll
        for (int g = 0; g < HID; g++)
            #pragma unroll
            for (int h = 0; h < HID; h++) w2t[g][h] = W[(16 + g * 8 + h) * 256];
        #pragma unroll
        for (int g = 0; g < HID; g++) w3[g] = W[(80 + g) * 256];
    }

    // Warp 0: exclusive prefix over the 144 active counts
    if (t < 32) {
        int base = t * 5;
        int c0 = (base + 0 < MTOT) ? g_cnt[base + 0] : 0;
        int c1 = (base + 1 < MTOT) ? g_cnt[base + 1] : 0;
        int c2 = (base + 2 < MTOT) ? g_cnt[base + 2] : 0;
        int c3 = (base + 3 < MTOT) ? g_cnt[base + 3] : 0;
        int c4 = (base + 4 < MTOT) ? g_cnt[base + 4] : 0;
        int l0 = c0, l1 = l0 + c1, l2 = l1 + c2, l3 = l2 + c3, l4 = l3 + c4;
        int x = l4;
        #pragma unroll
        for (int d = 1; d < 32; d <<= 1) {
            int y = __shfl_up_sync(0xffffffffu, x, d);
            if (lane >= d) x += y;
        }
        int excl = x - l4;
        if (base + 0 <= MTOT) s_off[base + 0] = excl;
        if (base + 1 <= MTOT) s_off[base + 1] = excl + l0;
        if (base + 2 <= MTOT) s_off[base + 2] = excl + l1;
        if (base + 3 <= MTOT) s_off[base + 3] = excl + l2;
        if (base + 4 <= MTOT) s_off[base + 4] = excl + l3;
    }
    __syncthreads();

    const int T = s_off[MTOT];
    const int chunk = (T + NB - 1) / NB;
    const int p0 = blockIdx.x * chunk;
    const int n  = min(p0 + chunk, T) - p0;
    if (n <= 0) return;

    // Preload this block's point metadata (one thread per point)
    if (t < n) {
        int p = p0 + t;
        int lo = 0, hi = MTOT;
        while (hi - lo > 1) { int mid = (lo + hi) >> 1; (s_off[mid] <= p) ? (lo = mid) : (hi = mid); }
        s_pm[t]  = lo;
        s_pts[t] = g_pts[lo * PSTRIDE + (p - s_off[lo])];
    }
    __syncthreads();

    const uint32_t sfb   = (uint32_t)__cvta_generic_to_shared(&s_f[0][0]);
    const uint32_t myoff = (uint32_t)(t * 8);

    // Prefetch points 0..2 (one commit group per point, empty groups kept)
    #pragma unroll
    for (int j = 0; j < 3; j++) {
        if (j < n)
            cp8(sfb + (uint32_t)j * 2048 + myoff,
                g_featT2 + (size_t)__float_as_int(s_pts[j].w) * 512 + t * 2);
        CP_COMMIT();
    }

    int cm = s_pm[0];
    float a0 = 0.0f, a1 = 0.0f;

    for (int i = 0; i < n; i++) {
        // Prefetch point i+3 into buffer (i+3)&3 (last read in iteration i-1,
        // separated from this clobber by iteration i-1's trailing barrier)
        if (i + 3 < n)
            cp8(sfb + (uint32_t)((i + 3) & 3) * 2048 + myoff,
                g_featT2 + (size_t)__float_as_int(s_pts[i + 3].w) * 512 + t * 2);
        CP_COMMIT();

        const float4 pt = s_pts[i];
        const int    m  = s_pm[i];
        if (m != cm) {   // flush partials on m transition
            atomicAdd(&out[(2 * bh)     * (CO * MTOT) + o * MTOT + cm], a0);
            atomicAdd(&out[(2 * bh + 1) * (CO * MTOT) + o * MTOT + cm], a1);
            a0 = 0.0f; a1 = 0.0f; cm = m;
        }
        const float x0 = pt.x, x1 = pt.y, bw = pt.z;

        // Tiny MLP: 2 -> 8 (sin) -> 8 (sin) -> 1; sins on MUFU pipe
        float h1[HID];
        #pragma unroll
        for (int h = 0; h < HID; h++)
            h1[h] = __sinf(fmaf(x0, w1a[h], x1 * w1b[h]));
        float val = 0.0f;
        #pragma unroll
        for (int g = 0; g < HID; g++) {
            float acc = 0.0f;
            #pragma unroll
            for (int h = 0; h < HID; h++) acc = fmaf(h1[h], w2t[g][h], acc);
            val = fmaf(__sinf(acc), w3[g], val);
        }
        float v = val * bw;

        CP_WAIT3();           // group i complete (<=3 newer pending)
        __syncthreads();      // all threads' waits done -> panel visible

        // Contraction: v[o,cc] via intra-warp shuffle, features from smem
        const float* fb = &s_f[i & 3][2 * bh];
        #pragma unroll
        for (int cc = 0; cc < CI; cc++) {
            float vv = __shfl_sync(0xffffffffu, v, (lane & 16) + cc);
            float2 f = *(const float2*)(fb + cc * 32);
            a0 = fmaf(vv, f.x, a0);
            a1 = fmaf(vv, f.y, a1);
        }
        __syncthreads();      // reads done before next iteration's clobber
    }

    atomicAdd(&out[(2 * bh)     * (CO * MTOT) + o * MTOT + cm], a0);
    atomicAdd(&out[(2 * bh + 1) * (CO * MTOT) + o * MTOT + cm], a1);
}

// ---------------------------------------------------------------------------
extern "C" void kernel_launch(void* const* d_in, const int* in_sizes, int n_in,
                              void* d_out, int out_size) {
    const float* feats = (const float*)d_in[0];  // (32, 16, 576)
    const float* locs  = (const float*)d_in[1];  // (144, 2)
    const float* qn    = (const float*)d_in[2];  // (24,)
    const float* qw    = (const float*)d_in[3];  // (24,)
    const float* W1    = (const float*)d_in[4];  // (16,16,2,8)
    const float* W2    = (const float*)d_in[5];  // (16,16,8,8)
    const float* W3    = (const float*)d_in[6];  // (16,16,8,1)
    float* out = (float*)d_out;                  // (32, 16, 144)

    qc_prep<<<PB_Z, 256>>>(feats, W1, W2, W3, locs, qn, qw, out);
    qc_main<<<NB, 256>>>(out);
}